// round 4
// baseline (speedup 1.0000x reference)
#include <cuda_runtime.h>
#include <math_constants.h>

// MeanMaxPooling: N=4, E=64, L=512, D=256
// in[0]: doc_state    (N, L, D) float32
// in[1]: nodes_mapping(N, E, L) float32 (0/1)
// in[2]: nodes_len    (N, E)    float32   (== sum(mask), recomputed via popc)
// out  : (N, E, 2*D)  float32  [0:D]=max over masked states (incl. 0), [D:2D]=mean

#define N_ 4
#define E_ 64
#define L_ 512
#define D_ 256
#define NW 8            // warps per CTA; warp w owns tokens [64w, 64w+64)

__global__ __launch_bounds__(NW * 32)
void meanmax_kernel(const float* __restrict__ doc_state,
                    const float* __restrict__ nodes_mapping,
                    const float* __restrict__ out_dummy_unused,
                    float* __restrict__ out)
{
    const int ne   = blockIdx.x;      // (n, e) pair, 0..255
    const int half = blockIdx.y;      // d half: 0 -> d[0:128), 1 -> d[128:256)
    const int n    = ne >> 6;
    const int tid  = threadIdx.x;
    const int w    = tid >> 5;        // warp = 64-token chunk
    const int lane = tid & 31;

    __shared__ float4 s_sum[NW][32];  // [warp][d/4 within half]  4 KB
    __shared__ float4 s_max[NW][32];  //                          4 KB
    __shared__ int    s_cnt[NW];

    // warp reads its 64 mask values (two coalesced 128B lines) -> 64-bit bitmask
    const float* mrow = nodes_mapping + (size_t)ne * L_ + w * 64;
    const float mv0 = mrow[lane];
    const float mv1 = mrow[32 + lane];
    const unsigned b0 = __ballot_sync(0xffffffffu, mv0 != 0.0f);
    const unsigned b1 = __ballot_sync(0xffffffffu, mv1 != 0.0f);
    unsigned long long mb = (unsigned long long)b0 |
                            ((unsigned long long)b1 << 32);
    if (lane == 0) s_cnt[w] = __popcll(mb);

    // lane owns float4 slot (half*32 + lane) of each token row
    const float4* doc4 = (const float4*)(doc_state + (size_t)n * L_ * D_)
                         + (half * 32 + lane);
    const int base = w * 64;

    float4 sum = make_float4(0.f, 0.f, 0.f, 0.f);
    float4 mx  = make_float4(-CUDART_INF_F, -CUDART_INF_F,
                             -CUDART_INF_F, -CUDART_INF_F);

    // gather: batches of 8 independent predicated 16B loads (mean cnt ~6.4)
    while (mb) {
        int  l[8];
        bool ok[8];
        #pragma unroll
        for (int j = 0; j < 8; ++j) {
            ok[j] = (mb != 0ull);
            l[j]  = ok[j] ? (__ffsll(mb) - 1) : 0;
            mb &= mb - 1ull;
        }
        float4 v[8];
        #pragma unroll
        for (int j = 0; j < 8; ++j)
            if (ok[j]) v[j] = doc4[(size_t)(base + l[j]) * (D_ / 4)];
        #pragma unroll
        for (int j = 0; j < 8; ++j) {
            if (ok[j]) {
                sum.x += v[j].x; sum.y += v[j].y;
                sum.z += v[j].z; sum.w += v[j].w;
                mx.x = fmaxf(mx.x, v[j].x); mx.y = fmaxf(mx.y, v[j].y);
                mx.z = fmaxf(mx.z, v[j].z); mx.w = fmaxf(mx.w, v[j].w);
            }
        }
    }

    s_sum[w][lane] = sum;
    s_max[w][lane] = mx;
    __syncthreads();

    // warp 0 -> max half, warp 1 -> sum half; lane j merges slot j of 8 partials
    if (tid < 64) {
        const bool is_max = (tid < 32);
        const int  j = lane;

        float4 r = is_max ? s_max[0][j] : s_sum[0][j];
        #pragma unroll
        for (int q = 1; q < NW; ++q) {
            const float4 p = is_max ? s_max[q][j] : s_sum[q][j];
            if (is_max) {
                r.x = fmaxf(r.x, p.x); r.y = fmaxf(r.y, p.y);
                r.z = fmaxf(r.z, p.z); r.w = fmaxf(r.w, p.w);
            } else {
                r.x += p.x; r.y += p.y; r.z += p.z; r.w += p.w;
            }
        }

        int tot = 0;
        #pragma unroll
        for (int q = 0; q < NW; ++q) tot += s_cnt[q];

        float4* orow4 = (float4*)(out + (size_t)ne * (2 * D_));
        if (is_max) {
            if (tot < L_) {             // any masked-out token => 0 joins the max
                r.x = fmaxf(r.x, 0.f); r.y = fmaxf(r.y, 0.f);
                r.z = fmaxf(r.z, 0.f); r.w = fmaxf(r.w, 0.f);
            }
            orow4[half * 32 + j] = r;
        } else {
            const float inv = 1.0f / (float)((tot > 0) ? tot : 1);
            r.x *= inv; r.y *= inv; r.z *= inv; r.w *= inv;
            orow4[(D_ / 4) + half * 32 + j] = r;
        }
    }
}

extern "C" void kernel_launch(void* const* d_in, const int* in_sizes, int n_in,
                              void* d_out, int out_size)
{
    const float* doc_state     = (const float*)d_in[0];
    const float* nodes_mapping = (const float*)d_in[1];
    const float* nodes_len     = (const float*)d_in[2];   // unused (recomputed)
    float* out = (float*)d_out;

    dim3 grid(N_ * E_, 2);
    dim3 block(NW * 32);
    meanmax_kernel<<<grid, block>>>(doc_state, nodes_mapping, nodes_len, out);
}